// round 11
// baseline (speedup 1.0000x reference)
#include <cuda_runtime.h>
#include <cuda_fp16.h>
#include <math.h>

#define NA 4096
#define NB 4096
#define NS 4

typedef unsigned long long u64;

// Scratch (device globals — allocation-free per harness rules)
__device__ __half g_Kh [(size_t)NA * NB];   // K[n][m]  = exp(-C[n][m]/eps), fp16
__device__ __half g_KTh[(size_t)NB * NA];   // KT[m][n] = K[n][m], fp16
__device__ float  g_u  [NS * NA];           // u = exp(f/eps), s-major
__device__ float  g_v  [NS * NB];           // v = exp(g/eps), s-major

// ---------------------------------------------------------------------------
// f32x2 packed helpers (sm_103a FFMA2 path — only reachable via PTX)
// ---------------------------------------------------------------------------
__device__ __forceinline__ u64 pack_f32x2(float lo, float hi) {
    u64 r;
    asm("mov.b64 %0, {%1, %2};" : "=l"(r) : "f"(lo), "f"(hi));
    return r;
}
__device__ __forceinline__ void unpack_f32x2(u64 v, float& lo, float& hi) {
    asm("mov.b64 {%0, %1}, %2;" : "=f"(lo), "=f"(hi) : "l"(v));
}
__device__ __forceinline__ void fma_f32x2(u64& acc, u64 a, u64 b) {
    asm("fma.rn.f32x2 %0, %1, %2, %0;" : "+l"(acc) : "l"(a), "l"(b));
}
__device__ __forceinline__ u64 h2_to_f32x2(__half2 h) {
    const float2 f = __half22float2(h);
    return pack_f32x2(f.x, f.y);
}

// ---------------------------------------------------------------------------
// cp.async helpers
// ---------------------------------------------------------------------------
__device__ __forceinline__ void cp_async16(unsigned saddr, const void* gptr) {
    asm volatile("cp.async.cg.shared.global [%0], [%1], 16;\n"
                 :: "r"(saddr), "l"(gptr));
}
__device__ __forceinline__ void cp_commit() {
    asm volatile("cp.async.commit_group;\n");
}
template <int N>
__device__ __forceinline__ void cp_wait() {
    asm volatile("cp.async.wait_group %0;\n" :: "n"(N));
}

// ---------------------------------------------------------------------------
// Kernel 1: K = exp(-C/eps) (fp16) and its transpose, tiled 32x32.
// ---------------------------------------------------------------------------
__global__ void expT_kernel(const float* __restrict__ C,
                            const float* __restrict__ eps_p) {
    __shared__ float tile[32][33];
    const float scale = -1.44269504088896340736f / eps_p[0];
    const int bx = blockIdx.x * 32, by = blockIdx.y * 32;
    const int tx = threadIdx.x, ty = threadIdx.y;             // (16, 16)

#pragma unroll
    for (int j = 0; j < 32; j += 16) {
        const int r = by + ty + j;
        const int c = bx + tx * 2;
        const float2 cv = *(const float2*)&C[(size_t)r * NB + c];
        const float e0 = exp2f(cv.x * scale);
        const float e1 = exp2f(cv.y * scale);
        *(__half2*)&g_Kh[(size_t)r * NB + c] = __floats2half2_rn(e0, e1);
        tile[ty + j][tx * 2]     = e0;
        tile[ty + j][tx * 2 + 1] = e1;
    }
    __syncthreads();
#pragma unroll
    for (int j = 0; j < 32; j += 16) {
        const int rr = ty + j;
        const int r  = bx + rr;
        const int c  = by + tx * 2;
        *(__half2*)&g_KTh[(size_t)r * NA + c] =
            __floats2half2_rn(tile[tx * 2][rr], tile[tx * 2 + 1][rr]);
    }
}

__global__ void init_v_kernel() {
    const int i = blockIdx.x * blockDim.x + threadIdx.x;
    if (i < NS * NB) g_v[i] = 1.0f;
}

// ---------------------------------------------------------------------------
// Kernel 3: one Sinkhorn half-step.
//   dir=0: u = alpha / (K  v)   |   dir=1: v = beta / (KT u)
// x staged in smem as *fp32* (64KB, cp.async copy, no converts, no scaling);
// parity-split layout: per s, even float4s at [0,512), odd at [512,1024), so
// the stride-2 read pattern becomes lane-consecutive (conflict-free LDS.128)
// and each float2 is directly a packed f32x2 FMA2 operand.
// 256 threads / 8 warps; warp = 4 rows x half-columns; 16 rows/block; grid 256.
// ---------------------------------------------------------------------------
__global__ void __launch_bounds__(256) phase_kernel(const int dir,
                                                    const float* __restrict__ tgt) {
    extern __shared__ float sx[];                  // NS*4096 fp32 = 64KB
    __shared__ float sred[8][16];
    const __half* __restrict__ M = dir ? g_KTh : g_Kh;
    const float*  __restrict__ x = dir ? g_u  : g_v;
    float*        __restrict__ out = dir ? g_v : g_u;

    const int tid = threadIdx.x;

    // Stage x via cp.async with parity split: global float4 j = s*1024 + i
    // -> slot = s*1024 + (i&1)*512 + (i>>1).
    {
        const unsigned sx_base = (unsigned)__cvta_generic_to_shared(sx);
        const float4* __restrict__ x4 = (const float4*)x;
#pragma unroll
        for (int j = tid; j < NS * 1024; j += 256) {
            const int i = j & 1023;
            const int slot = (j & ~1023) + ((i & 1) << 9) + (i >> 1);
            cp_async16(sx_base + (unsigned)slot * 16, x4 + j);
        }
        cp_commit();
    }

    const int warp = tid >> 5;            // 0..7
    const int lane = tid & 31;
    const int q    = warp >> 1;           // row-quad 0..3
    const int h    = warp & 1;            // column half
    const int row0 = blockIdx.x * 16 + q * 4;

    const uint4* __restrict__ mr[4] = {
        (const uint4*)(M + (size_t)(row0 + 0) * 4096),
        (const uint4*)(M + (size_t)(row0 + 1) * 4096),
        (const uint4*)(M + (size_t)(row0 + 2) * 4096),
        (const uint4*)(M + (size_t)(row0 + 3) * 4096)};

    cp_wait<0>();
    __syncthreads();

    const float4* __restrict__ sx4 = (const float4*)sx;

    // acc[r][s]: packed (even, odd) column-pair sums
    u64 acc[4][NS];
    const u64 z = pack_f32x2(0.f, 0.f);
#pragma unroll
    for (int r = 0; r < 4; ++r)
#pragma unroll
        for (int s = 0; s < NS; ++s) acc[r][s] = z;

    // Warp covers K-uint4 idx in [h*256, h*256+256): 8 lane-steps, batch 2.
#pragma unroll
    for (int step = 0; step < 8; step += 2) {
        uint4 kr[2][4];
#pragma unroll
        for (int b = 0; b < 2; ++b) {
            const int idx = h * 256 + (step + b) * 32 + lane;
#pragma unroll
            for (int r = 0; r < 4; ++r) kr[b][r] = mr[r][idx];
        }
#pragma unroll
        for (int b = 0; b < 2; ++b) {
            const int idx = h * 256 + (step + b) * 32 + lane;
            u64 kf[4][4];
#pragma unroll
            for (int r = 0; r < 4; ++r)
#pragma unroll
                for (int p = 0; p < 4; ++p)
                    kf[r][p] = h2_to_f32x2(((const __half2*)&kr[b][r])[p]);
#pragma unroll
            for (int s = 0; s < NS; ++s) {
                const float4 xe = sx4[s * 1024 + idx];        // cols 8i..8i+3
                const float4 xo = sx4[s * 1024 + 512 + idx];  // cols 8i+4..8i+7
                const u64 xp0 = pack_f32x2(xe.x, xe.y);
                const u64 xp1 = pack_f32x2(xe.z, xe.w);
                const u64 xp2 = pack_f32x2(xo.x, xo.y);
                const u64 xp3 = pack_f32x2(xo.z, xo.w);
#pragma unroll
                for (int r = 0; r < 4; ++r) {
                    fma_f32x2(acc[r][s], kf[r][0], xp0);
                    fma_f32x2(acc[r][s], kf[r][1], xp1);
                    fma_f32x2(acc[r][s], kf[r][2], xp2);
                    fma_f32x2(acc[r][s], kf[r][3], xp3);
                }
            }
        }
    }

    // Collapse pairs, butterfly-reduce, publish per-warp partials
    float a[4][NS];
#pragma unroll
    for (int r = 0; r < 4; ++r)
#pragma unroll
        for (int s = 0; s < NS; ++s) {
            float lo, hi;
            unpack_f32x2(acc[r][s], lo, hi);
            a[r][s] = lo + hi;
        }
#pragma unroll
    for (int r = 0; r < 4; ++r)
#pragma unroll
        for (int s = 0; s < NS; ++s)
#pragma unroll
            for (int o = 16; o > 0; o >>= 1)
                a[r][s] += __shfl_xor_sync(0xFFFFFFFFu, a[r][s], o);

    if (lane == 0) {
#pragma unroll
        for (int r = 0; r < 4; ++r)
#pragma unroll
            for (int s = 0; s < NS; ++s)
                sred[warp][r * 4 + s] = a[r][s];
    }
    __syncthreads();

    // Combine column halves: 64 threads, one output each
    if (tid < 64) {
        const int qq = tid >> 4;          // row-quad
        const int rs = tid & 15;          // r*4 + s
        const int r  = rs >> 2;
        const int s  = rs & 3;
        const float sum = sred[qq * 2][rs] + sred[qq * 2 + 1][rs];
        const int row = blockIdx.x * 16 + qq * 4 + r;
        out[s * 4096 + row] = tgt[s * 4096 + row] / sum;
    }
}

// ---------------------------------------------------------------------------
// Kernel 4: f = eps*log(u), g = eps*log(v)
// ---------------------------------------------------------------------------
__global__ void finalize_kernel(const float* __restrict__ eps_p,
                                float* __restrict__ out) {
    const int i = blockIdx.x * blockDim.x + threadIdx.x;
    const float eps = eps_p[0];
    if (i < NS * NA) {
        out[i]           = eps * logf(g_u[i]);
        out[i + NS * NA] = eps * logf(g_v[i]);
    }
}

// ---------------------------------------------------------------------------
extern "C" void kernel_launch(void* const* d_in, const int* in_sizes, int n_in,
                              void* d_out, int out_size) {
    const float* alpha = (const float*)d_in[0];   // (4, 4096)
    const float* beta  = (const float*)d_in[1];   // (4, 4096)
    const float* C     = (const float*)d_in[2];   // (4096, 4096)
    const float* eps   = (const float*)d_in[3];   // scalar
    float* out = (float*)d_out;                   // f (4,4096) then g (4,4096)

    const int smem = NS * 4096 * sizeof(float);   // 64KB dynamic
    cudaFuncSetAttribute(phase_kernel,
                         cudaFuncAttributeMaxDynamicSharedMemorySize, smem);

    expT_kernel<<<dim3(NB / 32, NA / 32), dim3(16, 16)>>>(C, eps);
    init_v_kernel<<<(NS * NB + 1023) / 1024, 1024>>>();

    for (int it = 0; it < 10; ++it) {
        phase_kernel<<<256, 256, smem>>>(0, alpha);  // u = alpha/(K v)
        phase_kernel<<<256, 256, smem>>>(1, beta);   // v = beta /(KT u)
    }

    finalize_kernel<<<(NS * NA + 255) / 256, 256>>>(eps, out);
}

// round 12
// speedup vs baseline: 1.7930x; 1.7930x over previous
#include <cuda_runtime.h>
#include <cuda_fp16.h>
#include <math.h>

#define NA 4096
#define NB 4096
#define NS 4
#define BK 512                     // K-tile columns
#define NTILE (4096 / BK)          // 8
#define KSTRIDE (BK + 8)           // padded halves per K-tile row (520)
#define XSTRIDE (4096 + 16)        // padded halves per x row (4112)

// Scratch (device globals — allocation-free per harness rules)
__device__ __half g_Kh [(size_t)NA * NB];   // K[n][m]  = exp(-C[n][m]/eps), fp16
__device__ __half g_KTh[(size_t)NB * NA];   // KT[m][n] = K[n][m], fp16
__device__ float  g_u  [NS * NA];           // u = exp(f/eps), s-major
__device__ float  g_v  [NS * NB];           // v = exp(g/eps), s-major

// ---------------------------------------------------------------------------
// cp.async helpers
// ---------------------------------------------------------------------------
__device__ __forceinline__ void cp_async16(unsigned saddr, const void* gptr) {
    asm volatile("cp.async.cg.shared.global [%0], [%1], 16;\n"
                 :: "r"(saddr), "l"(gptr));
}
__device__ __forceinline__ void cp_commit() {
    asm volatile("cp.async.commit_group;\n");
}
template <int N>
__device__ __forceinline__ void cp_wait() {
    asm volatile("cp.async.wait_group %0;\n" :: "n"(N));
}

// ---------------------------------------------------------------------------
// Kernel 1: K = exp(-C/eps) (fp16) and its transpose, tiled 32x32.
// ---------------------------------------------------------------------------
__global__ void expT_kernel(const float* __restrict__ C,
                            const float* __restrict__ eps_p) {
    __shared__ float tile[32][33];
    const float scale = -1.44269504088896340736f / eps_p[0];
    const int bx = blockIdx.x * 32, by = blockIdx.y * 32;
    const int tx = threadIdx.x, ty = threadIdx.y;             // (16, 16)

#pragma unroll
    for (int j = 0; j < 32; j += 16) {
        const int r = by + ty + j;
        const int c = bx + tx * 2;
        const float2 cv = *(const float2*)&C[(size_t)r * NB + c];
        const float e0 = exp2f(cv.x * scale);
        const float e1 = exp2f(cv.y * scale);
        *(__half2*)&g_Kh[(size_t)r * NB + c] = __floats2half2_rn(e0, e1);
        tile[ty + j][tx * 2]     = e0;
        tile[ty + j][tx * 2 + 1] = e1;
    }
    __syncthreads();
#pragma unroll
    for (int j = 0; j < 32; j += 16) {
        const int rr = ty + j;
        const int r  = bx + rr;
        const int c  = by + tx * 2;
        *(__half2*)&g_KTh[(size_t)r * NA + c] =
            __floats2half2_rn(tile[tx * 2][rr], tile[tx * 2 + 1][rr]);
    }
}

__global__ void init_v_kernel() {
    const int i = blockIdx.x * blockDim.x + threadIdx.x;
    if (i < NS * NB) g_v[i] = 1.0f;
}

// ---------------------------------------------------------------------------
// Kernel 3: one Sinkhorn half-step via tensor cores (HMMA m16n8k16).
//   dir=0: u = alpha / (K  v)    (x = v, scale 1)
//   dir=1: v = beta  / (KT u)    (x = u, scale 2^16 to keep fp16 normal)
// Block = 16 rows (one m16 tile), 256 threads / 8 warps.
// K streamed 16x512 tiles via cp.async double buffer (padded rows, bank-safe);
// A frags via ldmatrix.x4; B frags (x, n=S zero-padded to 8) via guarded LDS
// from padded fp16 x image; f32 accumulation in the C fragment.
// Warp w covers k16-steps [w*4, w*4+4) of each tile; cross-warp smem reduce.
// ---------------------------------------------------------------------------
__global__ void __launch_bounds__(256) phase_kernel(const int dir,
                                                    const float* __restrict__ tgt) {
    extern __shared__ __half sh[];
    __half* sx = sh;                                // NS * XSTRIDE halves
    __half* sk = sh + NS * XSTRIDE;                 // 2 * 16 * KSTRIDE halves
    float*  sred = (float*)(sk + 2 * 16 * KSTRIDE); // 8 * 16 * 4 floats

    const __half* __restrict__ M = dir ? g_KTh : g_Kh;
    const float*  __restrict__ x = dir ? g_u  : g_v;
    float*        __restrict__ out = dir ? g_v : g_u;
    const float sc = dir ? 65536.0f : 1.0f;

    const int tid  = threadIdx.x;
    const int warp = tid >> 5;
    const int lane = tid & 31;
    const int row0b = blockIdx.x * 16;
    const __half* __restrict__ Mrow = M + (size_t)row0b * 4096;

    // Stage x (fp32 -> scaled fp16) into padded layout: sx[s*XSTRIDE + k]
    {
        const float2* __restrict__ x2 = (const float2*)x;
        __half2* s2 = (__half2*)sx;                 // XSTRIDE even -> aligned
#pragma unroll
        for (int i = tid; i < NS * 2048; i += 256) {
            const int s = i >> 11, j = i & 2047;
            const float2 v = x2[i];
            s2[s * (XSTRIDE / 2) + j] = __floats2half2_rn(v.x * sc, v.y * sc);
        }
    }

    const unsigned sk_base = (unsigned)__cvta_generic_to_shared(sk);
#define ISSUE_TILE(t)                                                          \
    {                                                                          \
        const __half* gb = Mrow + (t) * BK;                                    \
        const unsigned bb = sk_base + ((t) & 1) * (16 * KSTRIDE * 2);          \
        _Pragma("unroll")                                                      \
        for (int g = tid; g < 1024; g += 256) {                                \
            const int r = g >> 6, c8 = (g & 63) << 3;                          \
            cp_async16(bb + (unsigned)(r * KSTRIDE + c8) * 2,                  \
                       gb + (size_t)r * 4096 + c8);                            \
        }                                                                      \
        cp_commit();                                                           \
    }

    ISSUE_TILE(0);

    // C fragment (f32): c0,c1 -> row lane/4, cols (lane%4)*2,+1
    //                   c2,c3 -> row lane/4+8, same cols
    float c0 = 0.f, c1 = 0.f, c2 = 0.f, c3 = 0.f;

    // ldmatrix lane-address precompute (within a tile buffer):
    // grp0: rows 0-7 @k+0 | grp1: rows 8-15 @k+0 | grp2: rows 0-7 @k+8 | grp3: rows 8-15 @k+8
    const int lm_row = (lane & 7) + ((lane >> 3) & 1) * 8;
    const int lm_kof = (lane >> 4) * 8;

    // B-frag source: s = lane>>2 (valid if <4), k-pair offset (lane&3)*2
    const int bs   = lane >> 2;
    const bool bok = bs < NS;
    const __half* __restrict__ bx = sx + bs * XSTRIDE + (lane & 3) * 2;

#pragma unroll
    for (int t = 0; t < NTILE; ++t) {
        if (t + 1 < NTILE) { ISSUE_TILE(t + 1); cp_wait<1>(); }
        else               { cp_wait<0>(); }
        __syncthreads();   // tile t ready (t=0 also covers x staging)

        const __half* kb = sk + (t & 1) * 16 * KSTRIDE;

#pragma unroll
        for (int j = 0; j < 4; ++j) {
            const int kloc = warp * 64 + j * 16;        // k16-step in tile
            // A frag via ldmatrix.x4
            unsigned a0, a1, a2, a3;
            {
                const __half* ap = kb + lm_row * KSTRIDE + kloc + lm_kof;
                const unsigned aaddr = (unsigned)__cvta_generic_to_shared(ap);
                asm volatile(
                    "ldmatrix.sync.aligned.m8n8.x4.shared.b16 {%0,%1,%2,%3}, [%4];"
                    : "=r"(a0), "=r"(a1), "=r"(a2), "=r"(a3) : "r"(aaddr));
            }
            // B frag: b0 = x[s][gk + (lane%4)*2 .. +1], b1 = same +8
            const int gk = t * BK + kloc;
            unsigned b0 = 0, b1 = 0;
            if (bok) {
                b0 = *(const unsigned*)(bx + gk);
                b1 = *(const unsigned*)(bx + gk + 8);
            }
            asm volatile(
                "mma.sync.aligned.m16n8k16.row.col.f32.f16.f16.f32 "
                "{%0,%1,%2,%3}, {%4,%5,%6,%7}, {%8,%9}, {%0,%1,%2,%3};"
                : "+f"(c0), "+f"(c1), "+f"(c2), "+f"(c3)
                : "r"(a0), "r"(a1), "r"(a2), "r"(a3), "r"(b0), "r"(b1));
        }
        __syncthreads();   // all reads of buffer (t&1) done before reuse
    }

    // Publish per-warp partial C tiles (only cols 0..3 = s are meaningful)
    if ((lane & 3) < 2) {
        const int r  = lane >> 2;
        const int cc = (lane & 3) * 2;
        float* sw = sred + warp * 64;        // [16 rows][4 s]
        sw[r * 4 + cc]           = c0;
        sw[r * 4 + cc + 1]       = c1;
        sw[(r + 8) * 4 + cc]     = c2;
        sw[(r + 8) * 4 + cc + 1] = c3;
    }
    __syncthreads();

    // Combine 8 warps: 64 threads, one output each
    if (tid < 64) {
        const int row = tid >> 2;
        const int s   = tid & 3;
        float sum = 0.f;
#pragma unroll
        for (int w = 0; w < 8; ++w) sum += sred[w * 64 + row * 4 + s];
        out[s * 4096 + row0b + row] = tgt[s * 4096 + row0b + row] * sc / sum;
    }
#undef ISSUE_TILE
}

// ---------------------------------------------------------------------------
// Kernel 4: f = eps*log(u), g = eps*log(v)
// ---------------------------------------------------------------------------
__global__ void finalize_kernel(const float* __restrict__ eps_p,
                                float* __restrict__ out) {
    const int i = blockIdx.x * blockDim.x + threadIdx.x;
    const float eps = eps_p[0];
    if (i < NS * NA) {
        out[i]           = eps * logf(g_u[i]);
        out[i + NS * NA] = eps * logf(g_v[i]);
    }
}

// ---------------------------------------------------------------------------
extern "C" void kernel_launch(void* const* d_in, const int* in_sizes, int n_in,
                              void* d_out, int out_size) {
    const float* alpha = (const float*)d_in[0];   // (4, 4096)
    const float* beta  = (const float*)d_in[1];   // (4, 4096)
    const float* C     = (const float*)d_in[2];   // (4096, 4096)
    const float* eps   = (const float*)d_in[3];   // scalar
    float* out = (float*)d_out;                   // f (4,4096) then g (4,4096)

    const int smem = (NS * XSTRIDE + 2 * 16 * KSTRIDE) * (int)sizeof(__half)
                   + 8 * 16 * 4 * (int)sizeof(float);   // ~68.4 KB
    cudaFuncSetAttribute(phase_kernel,
                         cudaFuncAttributeMaxDynamicSharedMemorySize, smem);

    expT_kernel<<<dim3(NB / 32, NA / 32), dim3(16, 16)>>>(C, eps);
    init_v_kernel<<<(NS * NB + 1023) / 1024, 1024>>>();

    for (int it = 0; it < 10; ++it) {
        phase_kernel<<<256, 256, smem>>>(0, alpha);  // u = alpha/(K v)
        phase_kernel<<<256, 256, smem>>>(1, beta);   // v = beta /(KT u)
    }

    finalize_kernel<<<(NS * NA + 255) / 256, 256>>>(eps, out);
}

// round 14
// speedup vs baseline: 1.8804x; 1.0488x over previous
#include <cuda_runtime.h>
#include <cuda_fp16.h>
#include <math.h>

#define NA 4096
#define NB 4096
#define NS 4
#define BK 512                     // K-tile columns
#define NTILE (4096 / BK)          // 8
#define NBUF 3                     // pipeline depth
#define KSTRIDE (BK + 8)           // padded halves per K-tile row (520)
#define XSTRIDE (4096 + 16)        // padded halves per x row (4112)

// Scratch (device globals — allocation-free per harness rules)
__device__ __half g_Kh [(size_t)NA * NB];   // K[n][m]  = exp(-C[n][m]/eps), fp16
__device__ __half g_KTh[(size_t)NB * NA];   // KT[m][n] = K[n][m], fp16
__device__ float  g_u  [NS * NA];           // u = exp(f/eps), s-major
__device__ float  g_v  [NS * NB];           // v = exp(g/eps), s-major

// ---------------------------------------------------------------------------
// cp.async helpers
// ---------------------------------------------------------------------------
__device__ __forceinline__ void cp_async16(unsigned saddr, const void* gptr) {
    asm volatile("cp.async.cg.shared.global [%0], [%1], 16;\n"
                 :: "r"(saddr), "l"(gptr));
}
__device__ __forceinline__ void cp_commit() {
    asm volatile("cp.async.commit_group;\n");
}
template <int N>
__device__ __forceinline__ void cp_wait() {
    asm volatile("cp.async.wait_group %0;\n" :: "n"(N));
}

__device__ __forceinline__ uint2 pack4h(float a, float b, float c, float d) {
    __half2 lo = __floats2half2_rn(a, b);
    __half2 hi = __floats2half2_rn(c, d);
    uint2 r;
    r.x = *(unsigned*)&lo;
    r.y = *(unsigned*)&hi;
    return r;
}

// ---------------------------------------------------------------------------
// Kernel 1: K = exp(-C/eps) (fp16) and its transpose.
// 64(cols) x 32(rows) tile, 256 threads, float4 loads, 8B packed stores.
// Transpose via scatter into a [col][row] fp32 smem tile (bank-conflict-free).
// ---------------------------------------------------------------------------
__global__ void __launch_bounds__(256) expT_kernel(const float* __restrict__ C,
                                                   const float* __restrict__ eps_p) {
    __shared__ float tt[64][33];              // [col][row], padded
    const float scale = -1.44269504088896340736f / eps_p[0];
    const int bx = blockIdx.x * 64;           // column base
    const int by = blockIdx.y * 32;           // row base
    const int tid = threadIdx.x;
    const int c4 = tid & 15;                  // float4 group (16*4 = 64 cols)
    const int r  = tid >> 4;                  // 0..15

#pragma unroll
    for (int j = 0; j < 2; ++j) {
        const int row = r + j * 16;
        const float4 cv = *(const float4*)&C[(size_t)(by + row) * NB + bx + c4 * 4];
        const float e0 = exp2f(cv.x * scale);
        const float e1 = exp2f(cv.y * scale);
        const float e2 = exp2f(cv.z * scale);
        const float e3 = exp2f(cv.w * scale);
        *(uint2*)&g_Kh[(size_t)(by + row) * NB + bx + c4 * 4] = pack4h(e0, e1, e2, e3);
        tt[c4 * 4 + 0][row] = e0;
        tt[c4 * 4 + 1][row] = e1;
        tt[c4 * 4 + 2][row] = e2;
        tt[c4 * 4 + 3][row] = e3;
    }
    __syncthreads();

    const int rg  = tid & 7;                  // 8 groups of 4 rows (32 rows)
    const int tc_ = tid >> 3;                 // 0..31
#pragma unroll
    for (int j = 0; j < 2; ++j) {
        const int tc = tc_ + j * 32;          // transposed row = orig col
        const float f0 = tt[tc][rg * 4 + 0];
        const float f1 = tt[tc][rg * 4 + 1];
        const float f2 = tt[tc][rg * 4 + 2];
        const float f3 = tt[tc][rg * 4 + 3];
        *(uint2*)&g_KTh[(size_t)(bx + tc) * NA + by + rg * 4] = pack4h(f0, f1, f2, f3);
    }
}

__global__ void init_v_kernel() {
    const int i = blockIdx.x * blockDim.x + threadIdx.x;
    if (i < NS * NB) g_v[i] = 1.0f;
}

// ---------------------------------------------------------------------------
// Kernel 3: one Sinkhorn half-step via tensor cores (HMMA m16n8k16).
//   dir=0: u = alpha / (K  v)    (x = v, scale 1)
//   dir=1: v = beta  / (KT u)    (x = u, scale 2^16 to keep fp16 normal)
// Block = 16 rows (one m16 tile), 256 threads / 8 warps.
// K streamed 16x512 tiles via 3-deep cp.async pipeline (padded rows);
// A frags via ldmatrix.x4; B frags (x, n=S zero-padded to 8) via guarded LDS.
// Warp w covers k16-steps [w*4, w*4+4) of each tile; cross-warp smem reduce.
// ---------------------------------------------------------------------------
__global__ void __launch_bounds__(256) phase_kernel(const int dir,
                                                    const float* __restrict__ tgt) {
    extern __shared__ __half sh[];
    __half* sx = sh;                                   // NS * XSTRIDE halves
    __half* sk = sh + NS * XSTRIDE;                    // NBUF * 16 * KSTRIDE
    float*  sred = (float*)(sk + NBUF * 16 * KSTRIDE); // 8 * 64 floats

    const __half* __restrict__ M = dir ? g_KTh : g_Kh;
    const float*  __restrict__ x = dir ? g_u  : g_v;
    float*        __restrict__ out = dir ? g_v : g_u;
    const float sc = dir ? 65536.0f : 1.0f;

    const int tid  = threadIdx.x;
    const int warp = tid >> 5;
    const int lane = tid & 31;
    const int row0b = blockIdx.x * 16;
    const __half* __restrict__ Mrow = M + (size_t)row0b * 4096;

    const unsigned sk_base = (unsigned)__cvta_generic_to_shared(sk);
#define ISSUE_TILE(t)                                                          \
    {                                                                          \
        const __half* gb = Mrow + (t) * BK;                                    \
        const unsigned bb = sk_base + ((t) % NBUF) * (16 * KSTRIDE * 2);       \
        _Pragma("unroll")                                                      \
        for (int g = tid; g < 1024; g += 256) {                                \
            const int r = g >> 6, c8 = (g & 63) << 3;                          \
            cp_async16(bb + (unsigned)(r * KSTRIDE + c8) * 2,                  \
                       gb + (size_t)r * 4096 + c8);                            \
        }                                                                      \
        cp_commit();                                                           \
    }

    // Start the DMA before the x-staging LDGs so the two overlap.
    ISSUE_TILE(0);
    ISSUE_TILE(1);

    // Stage x (fp32 -> scaled fp16) into padded layout: sx[s*XSTRIDE + k]
    {
        const float2* __restrict__ x2 = (const float2*)x;
        __half2* s2 = (__half2*)sx;                    // XSTRIDE even -> aligned
#pragma unroll
        for (int i = tid; i < NS * 2048; i += 256) {
            const int s = i >> 11, j = i & 2047;
            const float2 v = x2[i];
            s2[s * (XSTRIDE / 2) + j] = __floats2half2_rn(v.x * sc, v.y * sc);
        }
    }

    // C fragment (f32): c0,c1 -> row lane/4, cols (lane%4)*2,+1
    //                   c2,c3 -> row lane/4+8, same cols
    float c0 = 0.f, c1 = 0.f, c2 = 0.f, c3 = 0.f;

    // ldmatrix lane-address precompute (within a tile buffer)
    const int lm_row = (lane & 7) + ((lane >> 3) & 1) * 8;
    const int lm_kof = (lane >> 4) * 8;

    // B-frag source: s = lane>>2 (valid if <4), k-pair offset (lane&3)*2
    const int bs   = lane >> 2;
    const bool bok = bs < NS;
    const __half* __restrict__ bx = sx + bs * XSTRIDE + (lane & 3) * 2;

#pragma unroll
    for (int t = 0; t < NTILE; ++t) {
        if (t + 2 < NTILE) cp_wait<1>();
        else               cp_wait<0>();
        __syncthreads();   // tile t ready (t=0 also covers x staging)

        if (t + 2 < NTILE) ISSUE_TILE(t + 2);   // prefetch before compute

        const __half* kb = sk + (t % NBUF) * 16 * KSTRIDE;

#pragma unroll
        for (int j = 0; j < 4; ++j) {
            const int kloc = warp * 64 + j * 16;        // k16-step in tile
            unsigned a0, a1, a2, a3;
            {
                const __half* ap = kb + lm_row * KSTRIDE + kloc + lm_kof;
                const unsigned aaddr = (unsigned)__cvta_generic_to_shared(ap);
                asm volatile(
                    "ldmatrix.sync.aligned.m8n8.x4.shared.b16 {%0,%1,%2,%3}, [%4];"
                    : "=r"(a0), "=r"(a1), "=r"(a2), "=r"(a3) : "r"(aaddr));
            }
            const int gk = t * BK + kloc;
            unsigned b0 = 0, b1 = 0;
            if (bok) {
                b0 = *(const unsigned*)(bx + gk);
                b1 = *(const unsigned*)(bx + gk + 8);
            }
            asm volatile(
                "mma.sync.aligned.m16n8k16.row.col.f32.f16.f16.f32 "
                "{%0,%1,%2,%3}, {%4,%5,%6,%7}, {%8,%9}, {%0,%1,%2,%3};"
                : "+f"(c0), "+f"(c1), "+f"(c2), "+f"(c3)
                : "r"(a0), "r"(a1), "r"(a2), "r"(a3), "r"(b0), "r"(b1));
        }
        __syncthreads();   // all reads of buffer (t%NBUF) done before reuse
    }

    // Publish per-warp partial C tiles (only cols 0..3 = s are meaningful)
    if ((lane & 3) < 2) {
        const int r  = lane >> 2;
        const int cc = (lane & 3) * 2;
        float* sw = sred + warp * 64;        // [16 rows][4 s]
        sw[r * 4 + cc]           = c0;
        sw[r * 4 + cc + 1]       = c1;
        sw[(r + 8) * 4 + cc]     = c2;
        sw[(r + 8) * 4 + cc + 1] = c3;
    }
    __syncthreads();

    // Combine 8 warps: 64 threads, one output each
    if (tid < 64) {
        const int row = tid >> 2;
        const int s   = tid & 3;
        float sum = 0.f;
#pragma unroll
        for (int w = 0; w < 8; ++w) sum += sred[w * 64 + row * 4 + s];
        out[s * 4096 + row0b + row] = tgt[s * 4096 + row0b + row] * sc / sum;
    }
#undef ISSUE_TILE
}

// ---------------------------------------------------------------------------
// Kernel 4: f = eps*log(u), g = eps*log(v)
// ---------------------------------------------------------------------------
__global__ void finalize_kernel(const float* __restrict__ eps_p,
                                float* __restrict__ out) {
    const int i = blockIdx.x * blockDim.x + threadIdx.x;
    const float eps = eps_p[0];
    if (i < NS * NA) {
        out[i]           = eps * logf(g_u[i]);
        out[i + NS * NA] = eps * logf(g_v[i]);
    }
}

// ---------------------------------------------------------------------------
extern "C" void kernel_launch(void* const* d_in, const int* in_sizes, int n_in,
                              void* d_out, int out_size) {
    const float* alpha = (const float*)d_in[0];   // (4, 4096)
    const float* beta  = (const float*)d_in[1];   // (4, 4096)
    const float* C     = (const float*)d_in[2];   // (4096, 4096)
    const float* eps   = (const float*)d_in[3];   // scalar
    float* out = (float*)d_out;                   // f (4,4096) then g (4,4096)

    const int smem = (NS * XSTRIDE + NBUF * 16 * KSTRIDE) * (int)sizeof(__half)
                   + 8 * 64 * (int)sizeof(float);   // ~84.9 KB
    cudaFuncSetAttribute(phase_kernel,
                         cudaFuncAttributeMaxDynamicSharedMemorySize, smem);

    expT_kernel<<<dim3(NB / 64, NA / 32), 256>>>(C, eps);
    init_v_kernel<<<(NS * NB + 1023) / 1024, 1024>>>();

    for (int it = 0; it < 10; ++it) {
        phase_kernel<<<256, 256, smem>>>(0, alpha);  // u = alpha/(K v)
        phase_kernel<<<256, 256, smem>>>(1, beta);   // v = beta /(KT u)
    }

    finalize_kernel<<<(NS * NA + 255) / 256, 256>>>(eps, out);
}